// round 1
// baseline (speedup 1.0000x reference)
#include <cuda_runtime.h>
#include <cuda_bf16.h>
#include <float.h>
#include <math.h>

#define B_SEG 16
#define INC 128
#define HID 32

// Scratch (no allocations allowed)
__device__ float    g_sum [B_SEG * INC];
__device__ unsigned g_maxk[B_SEG * INC];
__device__ int      g_cnt [B_SEG];
__device__ float    g_gate[B_SEG * INC];

// Monotone float <-> unsigned key for atomicMax
__device__ __forceinline__ unsigned orderFloat(float f) {
    unsigned u = __float_as_uint(f);
    return (u & 0x80000000u) ? ~u : (u | 0x80000000u);
}
__device__ __forceinline__ float unorderFloat(unsigned k) {
    return (k & 0x80000000u) ? __uint_as_float(k & 0x7fffffffu)
                             : __uint_as_float(~k);
}

__global__ void init_kernel() {
    int t = threadIdx.x;
    for (int i = t; i < B_SEG * INC; i += blockDim.x) {
        g_sum[i]  = 0.0f;
        g_maxk[i] = 0u;   // key 0 < key(any real float)
    }
    if (t < B_SEG) g_cnt[t] = 0;
}

__device__ __forceinline__ void flush_acc(int seg, int c4,
                                          const float4& s, const float4& m) {
    if (seg < 0) return;
    float*    sp = &g_sum [seg * INC + c4 * 4];
    unsigned* mp = &g_maxk[seg * INC + c4 * 4];
    atomicAdd(sp + 0, s.x); atomicAdd(sp + 1, s.y);
    atomicAdd(sp + 2, s.z); atomicAdd(sp + 3, s.w);
    atomicMax(mp + 0, orderFloat(m.x)); atomicMax(mp + 1, orderFloat(m.y));
    atomicMax(mp + 2, orderFloat(m.z)); atomicMax(mp + 3, orderFloat(m.w));
}

// 256 threads: 8 rows per iter, 32 float4 lanes per row.
__global__ void reduce_kernel(const float4* __restrict__ f,
                              const int*    __restrict__ bidx,
                              int n_rows, int rows_per_block) {
    int t      = threadIdx.x;
    int rowoff = t >> 5;
    int c4     = t & 31;
    int r0 = blockIdx.x * rows_per_block;
    int r1 = min(r0 + rows_per_block, n_rows);

    __shared__ int cnt_s[B_SEG];
    if (t < B_SEG) cnt_s[t] = 0;
    __syncthreads();

    float4 sum = make_float4(0.f, 0.f, 0.f, 0.f);
    float4 mx  = make_float4(-FLT_MAX, -FLT_MAX, -FLT_MAX, -FLT_MAX);
    int cur = -1;

    for (int r = r0 + rowoff; r < r1; r += 8) {
        int    s = __ldg(&bidx[r]);
        float4 v = __ldg(&f[(size_t)r * 32 + c4]);
        if (s != cur) {
            flush_acc(cur, c4, sum, mx);
            cur = s;
            sum = make_float4(0.f, 0.f, 0.f, 0.f);
            mx  = make_float4(-FLT_MAX, -FLT_MAX, -FLT_MAX, -FLT_MAX);
        }
        sum.x += v.x; sum.y += v.y; sum.z += v.z; sum.w += v.w;
        mx.x = fmaxf(mx.x, v.x); mx.y = fmaxf(mx.y, v.y);
        mx.z = fmaxf(mx.z, v.z); mx.w = fmaxf(mx.w, v.w);
        if (c4 == 0) atomicAdd(&cnt_s[s], 1);
    }
    flush_acc(cur, c4, sum, mx);

    __syncthreads();
    if (t < B_SEG && cnt_s[t] > 0) atomicAdd(&g_cnt[t], cnt_s[t]);
}

// One block, 512 threads = 16 warps (one warp per segment, lane = hidden unit).
__global__ void gate_kernel(const float* __restrict__ W1,
                            const float* __restrict__ b1,
                            const float* __restrict__ W2,
                            const float* __restrict__ b2) {
    __shared__ float W1s[INC * HID];          // 16 KB, layout [c][h] (as given)
    __shared__ float mean_s[B_SEG * INC];     // 8 KB
    __shared__ float max_s [B_SEG * INC];     // 8 KB
    __shared__ float hidm[B_SEG * HID];       // 2 KB
    __shared__ float hidx[B_SEG * HID];       // 2 KB

    int tid = threadIdx.x;

    for (int i = tid; i < INC * HID; i += blockDim.x) W1s[i] = W1[i];
    for (int i = tid; i < B_SEG * INC; i += blockDim.x) {
        int b = i >> 7;
        int cnt = g_cnt[b];
        float inv = 1.0f / fmaxf((float)cnt, 1.0f);
        mean_s[i] = g_sum[i] * inv;
        max_s[i]  = (cnt > 0) ? unorderFloat(g_maxk[i]) : 0.0f;
    }
    __syncthreads();

    int b = tid >> 5;   // segment (16 warps)
    int h = tid & 31;   // hidden unit
    float am = b1[h], ax = b1[h];
    #pragma unroll 8
    for (int c = 0; c < INC; c++) {
        float w = W1s[c * HID + h];
        am = fmaf(mean_s[b * INC + c], w, am);
        ax = fmaf(max_s [b * INC + c], w, ax);
    }
    hidm[b * HID + h] = fmaxf(am, 0.0f);
    hidx[b * HID + h] = fmaxf(ax, 0.0f);
    __syncthreads();

    // 2048 outputs, 512 threads x 4
    #pragma unroll
    for (int k = 0; k < 4; k++) {
        int idx = tid + k * 512;
        int bb = idx >> 7;
        int c  = idx & 127;
        float om = b2[c], ox = b2[c];
        #pragma unroll 8
        for (int hh = 0; hh < HID; hh++) {
            float w = __ldg(&W2[hh * INC + c]);
            om = fmaf(hidm[bb * HID + hh], w, om);
            ox = fmaf(hidx[bb * HID + hh], w, ox);
        }
        float z = om + ox;
        g_gate[idx] = 1.0f / (1.0f + __expf(-z));
    }
}

// Streaming scale: out = feats * gate[batch_idx]. 4-way batched loads for MLP.
__global__ void scale_kernel(const float4* __restrict__ f,
                             const int*    __restrict__ bidx,
                             float4* __restrict__ out,
                             size_t nvec) {
    size_t base   = (size_t)blockIdx.x * blockDim.x + threadIdx.x;
    size_t stride = (size_t)gridDim.x * blockDim.x;
    const float4* gate4 = (const float4*)g_gate;

    size_t i0 = base;
    size_t i1 = base + stride;
    size_t i2 = base + 2 * stride;
    size_t i3 = base + 3 * stride;

    float4 v0, v1, v2, v3;
    int s0 = 0, s1 = 0, s2 = 0, s3 = 0;
    if (i0 < nvec) { v0 = __ldg(&f[i0]); s0 = __ldg(&bidx[i0 >> 5]); }
    if (i1 < nvec) { v1 = __ldg(&f[i1]); s1 = __ldg(&bidx[i1 >> 5]); }
    if (i2 < nvec) { v2 = __ldg(&f[i2]); s2 = __ldg(&bidx[i2 >> 5]); }
    if (i3 < nvec) { v3 = __ldg(&f[i3]); s3 = __ldg(&bidx[i3 >> 5]); }

    if (i0 < nvec) {
        float4 g = gate4[s0 * 32 + (i0 & 31)];
        v0.x *= g.x; v0.y *= g.y; v0.z *= g.z; v0.w *= g.w;
        out[i0] = v0;
    }
    if (i1 < nvec) {
        float4 g = gate4[s1 * 32 + (i1 & 31)];
        v1.x *= g.x; v1.y *= g.y; v1.z *= g.z; v1.w *= g.w;
        out[i1] = v1;
    }
    if (i2 < nvec) {
        float4 g = gate4[s2 * 32 + (i2 & 31)];
        v2.x *= g.x; v2.y *= g.y; v2.z *= g.z; v2.w *= g.w;
        out[i2] = v2;
    }
    if (i3 < nvec) {
        float4 g = gate4[s3 * 32 + (i3 & 31)];
        v3.x *= g.x; v3.y *= g.y; v3.z *= g.z; v3.w *= g.w;
        out[i3] = v3;
    }
}

extern "C" void kernel_launch(void* const* d_in, const int* in_sizes, int n_in,
                              void* d_out, int out_size) {
    const float* feats = (const float*)d_in[0];
    const int*   bidx  = (const int*)d_in[1];
    const float* W1    = (const float*)d_in[2];
    const float* b1    = (const float*)d_in[3];
    const float* W2    = (const float*)d_in[4];
    const float* b2    = (const float*)d_in[5];
    float* out = (float*)d_out;

    int n_rows = in_sizes[1];                   // N points
    size_t nvec = (size_t)n_rows * (INC / 4);   // float4 count

    init_kernel<<<1, 256>>>();

    int red_blocks = 2048;
    int rows_per_block = (n_rows + red_blocks - 1) / red_blocks;
    reduce_kernel<<<red_blocks, 256>>>((const float4*)feats, bidx,
                                       n_rows, rows_per_block);

    gate_kernel<<<1, 512>>>(W1, b1, W2, b2);

    int sthreads = 256;
    size_t per_launch = (size_t)sthreads * 4;
    int sblocks = (int)((nvec + per_launch - 1) / per_launch);
    scale_kernel<<<sblocks, sthreads>>>((const float4*)feats, bidx,
                                        (float4*)out, nvec);
}